// round 6
// baseline (speedup 1.0000x reference)
#include <cuda_runtime.h>
#include <math.h>

#define B 32
#define N 32768
#define D 128
#define CH 128
#define NCH (N / CH)          // 256 chunks
#define YSTRIDE (D + 4)       // 132 floats: pad to kill LDS.128 bank conflicts

// per-chunk softmax partials (no allocations allowed)
__device__ float g_cmax[B * NCH];        // [B][NCH]
__device__ float g_csum[B * NCH];        // [B][NCH]
__device__ float g_cvec[B * D * NCH];    // [B][D][NCH], 4 MB: coalesced reads in k_final

// ---------------------------------------------------------------------------
// K1: fused chunk kernel (scalar FFMA — R4-proven). One CTA per 128-n chunk.
//  Phase A: thread t owns n=base+t; dot(x_b, y_n) for all 32 b (y,x in smem)
//           -> logits -> chunk max -> exp -> chunk sum.
//  Phase B: thread t owns d=t; acc[b] = sum_n e[b][n] * y[n][d].
//  Stores transposed [b][d][c]: scattered, but hidden under the FMA stream.
// ---------------------------------------------------------------------------
__global__ __launch_bounds__(128) void k_chunk(const float* __restrict__ x,
                                               const float* __restrict__ al,
                                               const float* __restrict__ y) {
    extern __shared__ float smem[];
    float* ys = smem;                    // CH * YSTRIDE   (67.6 KB)
    float* xs = ys + CH * YSTRIDE;       // B * D          (16 KB)
    float* es = xs + B * D;              // B * CH         (16 KB)
    __shared__ float sA[B], sScale[B], sC[B], cm[B];
    __shared__ float wred[B][4];

    const int t = threadIdx.x;
    const int base = blockIdx.x * CH;

    // stage y chunk (coalesced float4, padded rows)
    const float4* y4 = reinterpret_cast<const float4*>(y + (size_t)base * D);
    #pragma unroll
    for (int i = t; i < CH * D / 4; i += 128) {
        int row = i >> 5;
        int c4  = i & 31;
        *reinterpret_cast<float4*>(&ys[row * YSTRIDE + c4 * 4]) = y4[i];
    }
    const float4* x4 = reinterpret_cast<const float4*>(x);
    #pragma unroll
    for (int i = t; i < B * D / 4; i += 128)
        reinterpret_cast<float4*>(xs)[i] = x4[i];
    __syncthreads();

    if (t < B) {
        float a = al[t];
        float var = 1.0f - a;
        float x2 = 0.f;
        #pragma unroll 8
        for (int d = 0; d < D; d++) { float v = xs[t * D + d]; x2 = fmaf(v, v, x2); }
        sA[t] = -(0.5f * (float)D * logf(var) + 0.5f / var * x2);
        sScale[t] = sqrtf(a) / var;
        sC[t] = 0.5f * a / var;
    }
    __syncthreads();

    // ---- Phase A: dots + logits (scalar FFMA) ----
    float dot[B];
    #pragma unroll
    for (int b = 0; b < B; b++) dot[b] = 0.f;
    float y2 = 0.f;

    const float4* yrow = reinterpret_cast<const float4*>(&ys[t * YSTRIDE]);
    const float4* xs4  = reinterpret_cast<const float4*>(xs);
    #pragma unroll 4
    for (int d4 = 0; d4 < D / 4; d4++) {
        float4 yv = yrow[d4];
        y2 = fmaf(yv.x, yv.x, fmaf(yv.y, yv.y, fmaf(yv.z, yv.z, fmaf(yv.w, yv.w, y2))));
        #pragma unroll
        for (int b = 0; b < B; b++) {
            float4 xv = xs4[b * (D / 4) + d4];   // broadcast across warp
            dot[b] = fmaf(xv.x, yv.x, dot[b]);
            dot[b] = fmaf(xv.y, yv.y, dot[b]);
            dot[b] = fmaf(xv.z, yv.z, dot[b]);
            dot[b] = fmaf(xv.w, yv.w, dot[b]);
        }
    }

    const int lane = t & 31, w = t >> 5;
    #pragma unroll
    for (int b = 0; b < B; b++) {
        float l = fmaf(sScale[b], dot[b], sA[b]) - sC[b] * y2;
        es[b * CH + t] = l;
        float m = l;
        #pragma unroll
        for (int o = 16; o > 0; o >>= 1) m = fmaxf(m, __shfl_xor_sync(0xffffffffu, m, o));
        if (lane == 0) wred[b][w] = m;
    }
    __syncthreads();
    if (t < B) {
        float m = fmaxf(fmaxf(wred[t][0], wred[t][1]), fmaxf(wred[t][2], wred[t][3]));
        cm[t] = m;
        g_cmax[t * NCH + blockIdx.x] = m;
    }
    __syncthreads();

    #pragma unroll
    for (int b = 0; b < B; b++)
        es[b * CH + t] = __expf(es[b * CH + t] - cm[b]);
    __syncthreads();

    #pragma unroll
    for (int j = 0; j < B / 4; j++) {
        int b = w * (B / 4) + j;
        float s = es[b * CH + lane] + es[b * CH + lane + 32]
                + es[b * CH + lane + 64] + es[b * CH + lane + 96];
        #pragma unroll
        for (int o = 16; o > 0; o >>= 1) s += __shfl_xor_sync(0xffffffffu, s, o);
        if (lane == 0) g_csum[b * NCH + blockIdx.x] = s;
    }

    // ---- Phase B: acc[b][d=t] = sum_n e[b][n] * y[n][d] ----
    float acc[B];
    #pragma unroll
    for (int b = 0; b < B; b++) acc[b] = 0.f;

    #pragma unroll 2
    for (int n4 = 0; n4 < CH / 4; n4++) {
        const int n = n4 * 4;
        float y0 = ys[(n + 0) * YSTRIDE + t];
        float y1 = ys[(n + 1) * YSTRIDE + t];
        float yv2 = ys[(n + 2) * YSTRIDE + t];
        float y3 = ys[(n + 3) * YSTRIDE + t];
        #pragma unroll
        for (int b = 0; b < B; b++) {
            float4 e = *reinterpret_cast<const float4*>(&es[b * CH + n]);  // broadcast
            acc[b] = fmaf(e.x, y0, acc[b]);
            acc[b] = fmaf(e.y, y1, acc[b]);
            acc[b] = fmaf(e.z, yv2, acc[b]);
            acc[b] = fmaf(e.w, y3, acc[b]);
        }
    }

    // store transposed [b][d][c]; scattered 4B stores, hidden under compute
    #pragma unroll
    for (int b = 0; b < B; b++)
        g_cvec[((size_t)b * D + t) * NCH + blockIdx.x] = acc[b];
}

// ---------------------------------------------------------------------------
// K2: finisher. Grid = B * (D/4) = 1024 CTAs, 128 threads.
//  CTA (b,g): block-parallel M_b, SE_b from chunk partials; warp w owns
//  d = 4g + w; lanes read float4 over chunks (coalesced 512B per iter).
// ---------------------------------------------------------------------------
__global__ __launch_bounds__(128) void k_final(const float* __restrict__ x,
                                               const float* __restrict__ al,
                                               float* __restrict__ out) {
    __shared__ float sc[NCH];
    __shared__ float red[4];
    __shared__ float sM, sSE;
    const int t = threadIdx.x, lane = t & 31, w = t >> 5;
    const int b = blockIdx.x >> 5;
    const int g = blockIdx.x & 31;

    float c0 = g_cmax[b * NCH + t];
    float c1 = g_cmax[b * NCH + t + 128];
    float m = fmaxf(c0, c1);
    #pragma unroll
    for (int o = 16; o > 0; o >>= 1) m = fmaxf(m, __shfl_xor_sync(0xffffffffu, m, o));
    if (lane == 0) red[w] = m;
    __syncthreads();
    if (t == 0) sM = fmaxf(fmaxf(red[0], red[1]), fmaxf(red[2], red[3]));
    __syncthreads();
    const float M = sM;

    float s0 = __expf(c0 - M);
    float s1 = __expf(c1 - M);
    sc[t] = s0;
    sc[t + 128] = s1;
    float ps = fmaf(s0, g_csum[b * NCH + t], s1 * g_csum[b * NCH + t + 128]);
    #pragma unroll
    for (int o = 16; o > 0; o >>= 1) ps += __shfl_xor_sync(0xffffffffu, ps, o);
    if (lane == 0) red[w] = ps;
    __syncthreads();
    if (t == 0) sSE = red[0] + red[1] + red[2] + red[3];
    __syncthreads();

    // warp-per-output reduction, float4 over chunks
    const int d = g * 4 + w;
    const float4* pv4 = reinterpret_cast<const float4*>(g_cvec + ((size_t)b * D + d) * NCH);
    const float4* sc4 = reinterpret_cast<const float4*>(sc);
    float v = 0.f;
    #pragma unroll
    for (int j = 0; j < NCH / 128; j++) {       // 2 iters: lanes cover 128 chunks/iter
        const int c4 = j * 32 + lane;
        float4 pvv = pv4[c4];
        float4 scv = sc4[c4];
        v = fmaf(scv.x, pvv.x, v);
        v = fmaf(scv.y, pvv.y, v);
        v = fmaf(scv.z, pvv.z, v);
        v = fmaf(scv.w, pvv.w, v);
    }
    #pragma unroll
    for (int o = 16; o > 0; o >>= 1) v += __shfl_xor_sync(0xffffffffu, v, o);

    if (lane == 0) {
        float a = al[b];
        float var = 1.f - a;
        out[b * D + d] = (x[b * D + d] - sqrtf(a) * (v / sSE)) * rsqrtf(var);
    }
}

extern "C" void kernel_launch(void* const* d_in, const int* in_sizes, int n_in,
                              void* d_out, int out_size) {
    const float* x  = (const float*)d_in[0];   // inputs [B, D]
    const float* al = (const float*)d_in[1];   // alphas [B]
    const float* y  = (const float*)d_in[2];   // data_batch [N, D]
    float* out = (float*)d_out;                // [B, D]

    const size_t SMEM = (CH * YSTRIDE + B * D + B * CH) * sizeof(float);  // ~98 KB
    cudaFuncSetAttribute(k_chunk, cudaFuncAttributeMaxDynamicSharedMemorySize, (int)SMEM);

    k_chunk<<<NCH, 128, SMEM>>>(x, al, y);
    k_final<<<B * (D / 4), 128>>>(x, al, out);
}

// round 7
// speedup vs baseline: 1.1644x; 1.1644x over previous
#include <cuda_runtime.h>
#include <math.h>

#define B 32
#define N 32768
#define D 128
#define CH 128
#define NCH (N / CH)          // 256 chunks
#define NCG 8                 // chunk groups in stage-1 reduce
#define CPG (NCH / NCG)       // 32 chunks per group
#define YSTRIDE (D + 4)       // 132 floats: pad to kill LDS.128 bank conflicts

typedef unsigned long long u64;

// scratch (no allocations allowed)
__device__ float g_cmax[B * NCH];        // [B][NCH]
__device__ float g_csum[B * NCH];        // [B][NCH]
__device__ float g_cvec[NCH * B * D];    // [C][B][D], 4 MB — coalesced stores
__device__ float g_pvec2[B * NCG * D];   // [B][CG][D], 128 KB

__device__ __forceinline__ u64 fma2(u64 a, u64 b, u64 c) {
    u64 d;
    asm("fma.rn.f32x2 %0, %1, %2, %3;" : "=l"(d) : "l"(a), "l"(b), "l"(c));
    return d;
}
__device__ __forceinline__ u64 pk(float lo, float hi) {
    u64 r;
    asm("mov.b64 %0, {%1, %2};" : "=l"(r) : "f"(lo), "f"(hi));
    return r;
}
__device__ __forceinline__ float hsum2(u64 v) {
    float lo, hi;
    asm("mov.b64 {%0, %1}, %2;" : "=f"(lo), "=f"(hi) : "l"(v));
    return lo + hi;
}

// ---------------------------------------------------------------------------
// K1: fused chunk kernel. FFMA2 math, coalesced [c][b][d] stores.
// ---------------------------------------------------------------------------
__global__ __launch_bounds__(128, 2) void k_chunk(const float* __restrict__ x,
                                                  const float* __restrict__ al,
                                                  const float* __restrict__ y) {
    extern __shared__ float smem[];
    float* ys = smem;                    // CH * YSTRIDE   (67.6 KB)
    float* xs = ys + CH * YSTRIDE;       // B * D          (16 KB)
    float* es = xs + B * D;              // B * CH         (16 KB)
    __shared__ float sA[B], sScale[B], sC[B], cm[B];
    __shared__ float wred[B][4];

    const int t = threadIdx.x;
    const int base = blockIdx.x * CH;

    const float4* y4 = reinterpret_cast<const float4*>(y + (size_t)base * D);
    #pragma unroll
    for (int i = t; i < CH * D / 4; i += 128) {
        int row = i >> 5;
        int c4  = i & 31;
        *reinterpret_cast<float4*>(&ys[row * YSTRIDE + c4 * 4]) = y4[i];
    }
    const float4* x4 = reinterpret_cast<const float4*>(x);
    #pragma unroll
    for (int i = t; i < B * D / 4; i += 128)
        reinterpret_cast<float4*>(xs)[i] = x4[i];
    __syncthreads();

    if (t < B) {
        float a = al[t];
        float var = 1.0f - a;
        float x2 = 0.f;
        #pragma unroll 8
        for (int d = 0; d < D; d++) { float v = xs[t * D + d]; x2 = fmaf(v, v, x2); }
        sA[t] = -(0.5f * (float)D * logf(var) + 0.5f / var * x2);
        sScale[t] = sqrtf(a) / var;
        sC[t] = 0.5f * a / var;
    }
    __syncthreads();

    // ---- Phase A: dots via f32x2 ----
    u64 dot2[B];
    #pragma unroll
    for (int b = 0; b < B; b++) dot2[b] = 0ull;
    u64 y2a = 0ull, y2b = 0ull;

    const ulonglong2* yrow2 = reinterpret_cast<const ulonglong2*>(&ys[t * YSTRIDE]);
    const ulonglong2* xs2   = reinterpret_cast<const ulonglong2*>(xs);
    #pragma unroll 4
    for (int d4 = 0; d4 < D / 4; d4++) {
        ulonglong2 yv = yrow2[d4];
        y2a = fma2(yv.x, yv.x, y2a);
        y2b = fma2(yv.y, yv.y, y2b);
        #pragma unroll
        for (int b = 0; b < B; b++) {
            ulonglong2 xv = xs2[b * (D / 4) + d4];   // broadcast
            dot2[b] = fma2(xv.x, yv.x, dot2[b]);
            dot2[b] = fma2(xv.y, yv.y, dot2[b]);
        }
    }
    const float y2 = hsum2(y2a) + hsum2(y2b);

    const int lane = t & 31, w = t >> 5;
    #pragma unroll
    for (int b = 0; b < B; b++) {
        float l = fmaf(sScale[b], hsum2(dot2[b]), sA[b]) - sC[b] * y2;
        es[b * CH + t] = l;
        float m = l;
        #pragma unroll
        for (int o = 16; o > 0; o >>= 1) m = fmaxf(m, __shfl_xor_sync(0xffffffffu, m, o));
        if (lane == 0) wred[b][w] = m;
    }
    __syncthreads();
    if (t < B) {
        float m = fmaxf(fmaxf(wred[t][0], wred[t][1]), fmaxf(wred[t][2], wred[t][3]));
        cm[t] = m;
        g_cmax[t * NCH + blockIdx.x] = m;
    }
    __syncthreads();

    #pragma unroll
    for (int b = 0; b < B; b++)
        es[b * CH + t] = __expf(es[b * CH + t] - cm[b]);
    __syncthreads();

    #pragma unroll
    for (int j = 0; j < B / 4; j++) {
        int b = w * (B / 4) + j;
        float s = es[b * CH + lane] + es[b * CH + lane + 32]
                + es[b * CH + lane + 64] + es[b * CH + lane + 96];
        #pragma unroll
        for (int o = 16; o > 0; o >>= 1) s += __shfl_xor_sync(0xffffffffu, s, o);
        if (lane == 0) g_csum[b * NCH + blockIdx.x] = s;
    }

    // ---- Phase B: acc[b][d=t] via f32x2, pairing adjacent n ----
    u64 acc2[B];
    #pragma unroll
    for (int b = 0; b < B; b++) acc2[b] = 0ull;

    #pragma unroll 2
    for (int n4 = 0; n4 < CH / 4; n4++) {
        const int n = n4 * 4;
        u64 yp0 = pk(ys[(n + 0) * YSTRIDE + t], ys[(n + 1) * YSTRIDE + t]);
        u64 yp1 = pk(ys[(n + 2) * YSTRIDE + t], ys[(n + 3) * YSTRIDE + t]);
        #pragma unroll
        for (int b = 0; b < B; b++) {
            ulonglong2 e2 = *reinterpret_cast<const ulonglong2*>(&es[b * CH + n]); // broadcast
            acc2[b] = fma2(e2.x, yp0, acc2[b]);
            acc2[b] = fma2(e2.y, yp1, acc2[b]);
        }
    }

    // coalesced stores: [c][b][d], 512B per b
    float* pv = g_cvec + (size_t)blockIdx.x * B * D;
    #pragma unroll
    for (int b = 0; b < B; b++)
        pv[b * D + t] = hsum2(acc2[b]);
}

// block-parallel global max over one b row of g_cmax (128 threads)
__device__ __forceinline__ float block_max_cmax(int b, int t, int lane, int w,
                                                float* red, float& c0, float& c1) {
    __shared__ float sMx;
    c0 = g_cmax[b * NCH + t];
    c1 = g_cmax[b * NCH + t + 128];
    float m = fmaxf(c0, c1);
    #pragma unroll
    for (int o = 16; o > 0; o >>= 1) m = fmaxf(m, __shfl_xor_sync(0xffffffffu, m, o));
    if (lane == 0) red[w] = m;
    __syncthreads();
    if (t == 0) sMx = fmaxf(fmaxf(red[0], red[1]), fmaxf(red[2], red[3]));
    __syncthreads();
    return sMx;
}

// ---------------------------------------------------------------------------
// K2: stage-1 reduce. Grid = B * NCG = 256 CTAs, 128 threads (t = d).
//  CTA (b, cg): computes M_b + scales, sums its 32 chunks with fully
//  coalesced 512B reads, writes partial [b][cg][d].
// ---------------------------------------------------------------------------
__global__ __launch_bounds__(128) void k_part() {
    __shared__ float sc[NCH];
    __shared__ float red[4];
    const int t = threadIdx.x, lane = t & 31, w = t >> 5;
    const int b = blockIdx.x >> 3;
    const int cg = blockIdx.x & (NCG - 1);

    float c0, c1;
    const float M = block_max_cmax(b, t, lane, w, red, c0, c1);
    sc[t] = __expf(c0 - M);
    sc[t + 128] = __expf(c1 - M);
    __syncthreads();

    float v = 0.f;
    #pragma unroll
    for (int j = 0; j < CPG; j++) {
        const int c = cg * CPG + j;
        v = fmaf(sc[c], g_cvec[((size_t)c * B + b) * D + t], v);  // 512B coalesced
    }
    g_pvec2[(b * NCG + cg) * D + t] = v;
}

// ---------------------------------------------------------------------------
// K3: stage-2. Grid = B, 128 threads (t = d). Recomputes M, SE; sums the
//  NCG partials; epilogue.
// ---------------------------------------------------------------------------
__global__ __launch_bounds__(128) void k_fin2(const float* __restrict__ x,
                                              const float* __restrict__ al,
                                              float* __restrict__ out) {
    __shared__ float red[4];
    __shared__ float sSE;
    const int t = threadIdx.x, lane = t & 31, w = t >> 5;
    const int b = blockIdx.x;

    float c0, c1;
    const float M = block_max_cmax(b, t, lane, w, red, c0, c1);

    float ps = fmaf(__expf(c0 - M), g_csum[b * NCH + t],
                    __expf(c1 - M) * g_csum[b * NCH + t + 128]);
    #pragma unroll
    for (int o = 16; o > 0; o >>= 1) ps += __shfl_xor_sync(0xffffffffu, ps, o);
    if (lane == 0) red[w] = ps;
    __syncthreads();
    if (t == 0) sSE = red[0] + red[1] + red[2] + red[3];
    __syncthreads();

    float v = 0.f;
    #pragma unroll
    for (int cg = 0; cg < NCG; cg++)
        v += g_pvec2[(b * NCG + cg) * D + t];   // MLP=8, coalesced

    float a = al[b];
    float var = 1.f - a;
    out[b * D + t] = (x[b * D + t] - sqrtf(a) * (v / sSE)) * rsqrtf(var);
}

extern "C" void kernel_launch(void* const* d_in, const int* in_sizes, int n_in,
                              void* d_out, int out_size) {
    const float* x  = (const float*)d_in[0];   // inputs [B, D]
    const float* al = (const float*)d_in[1];   // alphas [B]
    const float* y  = (const float*)d_in[2];   // data_batch [N, D]
    float* out = (float*)d_out;                // [B, D]

    const size_t SMEM = (CH * YSTRIDE + B * D + B * CH) * sizeof(float);  // ~98 KB
    cudaFuncSetAttribute(k_chunk, cudaFuncAttributeMaxDynamicSharedMemorySize, (int)SMEM);

    k_chunk<<<NCH, 128, SMEM>>>(x, al, y);
    k_part<<<B * NCG, 128>>>();
    k_fin2<<<B, 128>>>(x, al, out);
}

// round 8
// speedup vs baseline: 1.3949x; 1.1979x over previous
#include <cuda_runtime.h>
#include <math.h>

#define B 32
#define N 32768
#define D 128
#define CH 128
#define NCH (N / CH)          // 256 chunks
#define NCG 8                 // chunk groups in stage-1 reduce
#define CPG (NCH / NCG)       // 32 chunks per group
#define YSTRIDE (D + 4)       // 132 floats: conflict-free LDS.128 row reads

// scratch (no allocations allowed)
__device__ float g_cmax[B * NCH];        // [B][NCH]
__device__ float g_csum[B * NCH];        // [B][NCH]
__device__ float g_cvec[NCH * B * D];    // [C][B][D] — coalesced stores
__device__ float g_pvec2[B * NCG * D];   // [B][CG][D]

// ---------------------------------------------------------------------------
// K1: fused chunk kernel, 2x16 register tiling (scalar FFMA).
//  Thread t: bg = t>>6 selects b-half (16 b's), tt = t&63.
//  Phase A: owns n-rows tt and tt+64; dot[2][16].
//  Phase B: owns d-cols tt and tt+64; acc[2][16].
// ---------------------------------------------------------------------------
__global__ __launch_bounds__(128, 2) void k_chunk(const float* __restrict__ x,
                                                  const float* __restrict__ al,
                                                  const float* __restrict__ y) {
    extern __shared__ float smem[];
    float* ys = smem;                    // CH * YSTRIDE   (67.6 KB)
    float* xs = ys + CH * YSTRIDE;       // B * D          (16 KB)
    float* es = xs + B * D;              // B * CH         (16 KB)
    __shared__ float sA[B], sScale[B], sC[B], cm[B];

    const int t = threadIdx.x;
    const int base = blockIdx.x * CH;
    const int bg = t >> 6;               // 0/1: which 16 b's
    const int tt = t & 63;
    const int bbase = bg * 16;

    // stage y chunk (coalesced float4, padded rows)
    const float4* y4 = reinterpret_cast<const float4*>(y + (size_t)base * D);
    #pragma unroll
    for (int i = t; i < CH * D / 4; i += 128) {
        int row = i >> 5;
        int c4  = i & 31;
        *reinterpret_cast<float4*>(&ys[row * YSTRIDE + c4 * 4]) = y4[i];
    }
    const float4* x4 = reinterpret_cast<const float4*>(x);
    #pragma unroll
    for (int i = t; i < B * D / 4; i += 128)
        reinterpret_cast<float4*>(xs)[i] = x4[i];
    __syncthreads();

    if (t < B) {
        float a = al[t];
        float var = 1.0f - a;
        float x2 = 0.f;
        #pragma unroll 8
        for (int d = 0; d < D; d++) { float v = xs[t * D + d]; x2 = fmaf(v, v, x2); }
        sA[t] = -(0.5f * (float)D * logf(var) + 0.5f / var * x2);
        sScale[t] = sqrtf(a) / var;
        sC[t] = 0.5f * a / var;
    }
    __syncthreads();

    // ---- Phase A: dot[2][16] over d. 18 LDS.128 per iter for 128 FMAs ----
    float dot0[16], dot1[16];
    #pragma unroll
    for (int j = 0; j < 16; j++) { dot0[j] = 0.f; dot1[j] = 0.f; }
    float y2n0 = 0.f, y2n1 = 0.f;

    const float4* yr0 = reinterpret_cast<const float4*>(&ys[tt * YSTRIDE]);
    const float4* yr1 = reinterpret_cast<const float4*>(&ys[(tt + 64) * YSTRIDE]);
    const float4* xs4 = reinterpret_cast<const float4*>(xs);
    #pragma unroll 4
    for (int d4 = 0; d4 < D / 4; d4++) {
        float4 a0 = yr0[d4];
        float4 a1 = yr1[d4];
        y2n0 = fmaf(a0.x, a0.x, fmaf(a0.y, a0.y, fmaf(a0.z, a0.z, fmaf(a0.w, a0.w, y2n0))));
        y2n1 = fmaf(a1.x, a1.x, fmaf(a1.y, a1.y, fmaf(a1.z, a1.z, fmaf(a1.w, a1.w, y2n1))));
        #pragma unroll
        for (int j = 0; j < 16; j++) {
            float4 xv = xs4[(bbase + j) * (D / 4) + d4];   // warp broadcast
            dot0[j] = fmaf(xv.x, a0.x, dot0[j]);
            dot0[j] = fmaf(xv.y, a0.y, dot0[j]);
            dot0[j] = fmaf(xv.z, a0.z, dot0[j]);
            dot0[j] = fmaf(xv.w, a0.w, dot0[j]);
            dot1[j] = fmaf(xv.x, a1.x, dot1[j]);
            dot1[j] = fmaf(xv.y, a1.y, dot1[j]);
            dot1[j] = fmaf(xv.z, a1.z, dot1[j]);
            dot1[j] = fmaf(xv.w, a1.w, dot1[j]);
        }
    }

    // logits -> es (raw)
    #pragma unroll
    for (int j = 0; j < 16; j++) {
        const int b = bbase + j;
        es[b * CH + tt]      = fmaf(sScale[b], dot0[j], sA[b]) - sC[b] * y2n0;
        es[b * CH + tt + 64] = fmaf(sScale[b], dot1[j], sA[b]) - sC[b] * y2n1;
    }
    __syncthreads();

    // max pass: warp w handles b = w*8..w*8+7
    const int lane = t & 31, w = t >> 5;
    #pragma unroll
    for (int j = 0; j < 8; j++) {
        const int b = w * 8 + j;
        float m = fmaxf(fmaxf(es[b * CH + lane], es[b * CH + lane + 32]),
                        fmaxf(es[b * CH + lane + 64], es[b * CH + lane + 96]));
        #pragma unroll
        for (int o = 16; o > 0; o >>= 1) m = fmaxf(m, __shfl_xor_sync(0xffffffffu, m, o));
        if (lane == 0) { cm[b] = m; g_cmax[b * NCH + blockIdx.x] = m; }
    }
    __syncthreads();

    // exp in place
    #pragma unroll
    for (int k = 0; k < B; k++)
        es[k * CH + t] = __expf(es[k * CH + t] - cm[k]);
    __syncthreads();

    // chunk sum per b
    #pragma unroll
    for (int j = 0; j < 8; j++) {
        const int b = w * 8 + j;
        float s = es[b * CH + lane] + es[b * CH + lane + 32]
                + es[b * CH + lane + 64] + es[b * CH + lane + 96];
        #pragma unroll
        for (int o = 16; o > 0; o >>= 1) s += __shfl_xor_sync(0xffffffffu, s, o);
        if (lane == 0) g_csum[b * NCH + blockIdx.x] = s;
    }

    // ---- Phase B: acc[2][16]; d0 = tt, d1 = tt+64. 24 LDS per 128 FMAs ----
    float acc0[16], acc1[16];
    #pragma unroll
    for (int j = 0; j < 16; j++) { acc0[j] = 0.f; acc1[j] = 0.f; }

    #pragma unroll 2
    for (int n4 = 0; n4 < CH / 4; n4++) {
        const int n = n4 * 4;
        float p0 = ys[(n + 0) * YSTRIDE + tt];
        float p1 = ys[(n + 1) * YSTRIDE + tt];
        float p2 = ys[(n + 2) * YSTRIDE + tt];
        float p3 = ys[(n + 3) * YSTRIDE + tt];
        float q0 = ys[(n + 0) * YSTRIDE + tt + 64];
        float q1 = ys[(n + 1) * YSTRIDE + tt + 64];
        float q2 = ys[(n + 2) * YSTRIDE + tt + 64];
        float q3 = ys[(n + 3) * YSTRIDE + tt + 64];
        #pragma unroll
        for (int j = 0; j < 16; j++) {
            float4 e = *reinterpret_cast<const float4*>(&es[(bbase + j) * CH + n]); // broadcast
            acc0[j] = fmaf(e.x, p0, acc0[j]);
            acc0[j] = fmaf(e.y, p1, acc0[j]);
            acc0[j] = fmaf(e.z, p2, acc0[j]);
            acc0[j] = fmaf(e.w, p3, acc0[j]);
            acc1[j] = fmaf(e.x, q0, acc1[j]);
            acc1[j] = fmaf(e.y, q1, acc1[j]);
            acc1[j] = fmaf(e.z, q2, acc1[j]);
            acc1[j] = fmaf(e.w, q3, acc1[j]);
        }
    }

    // coalesced stores: [c][b][d]
    float* pv = g_cvec + (size_t)blockIdx.x * B * D;
    #pragma unroll
    for (int j = 0; j < 16; j++) {
        pv[(bbase + j) * D + tt]      = acc0[j];
        pv[(bbase + j) * D + tt + 64] = acc1[j];
    }
}

// block-parallel global max over one b row of g_cmax (128 threads)
__device__ __forceinline__ float block_max_cmax(int b, int t, int lane, int w,
                                                float* red, float& c0, float& c1) {
    __shared__ float sMx;
    c0 = g_cmax[b * NCH + t];
    c1 = g_cmax[b * NCH + t + 128];
    float m = fmaxf(c0, c1);
    #pragma unroll
    for (int o = 16; o > 0; o >>= 1) m = fmaxf(m, __shfl_xor_sync(0xffffffffu, m, o));
    if (lane == 0) red[w] = m;
    __syncthreads();
    if (t == 0) sMx = fmaxf(fmaxf(red[0], red[1]), fmaxf(red[2], red[3]));
    __syncthreads();
    return sMx;
}

// ---------------------------------------------------------------------------
// K2: stage-1 reduce. Grid = B*NCG = 256 CTAs, 128 threads (t = d).
// ---------------------------------------------------------------------------
__global__ __launch_bounds__(128) void k_part() {
    __shared__ float sc[NCH];
    __shared__ float red[4];
    const int t = threadIdx.x, lane = t & 31, w = t >> 5;
    const int b = blockIdx.x >> 3;
    const int cg = blockIdx.x & (NCG - 1);

    float c0, c1;
    const float M = block_max_cmax(b, t, lane, w, red, c0, c1);
    sc[t] = __expf(c0 - M);
    sc[t + 128] = __expf(c1 - M);
    __syncthreads();

    float v = 0.f;
    #pragma unroll
    for (int j = 0; j < CPG; j++) {
        const int c = cg * CPG + j;
        v = fmaf(sc[c], g_cvec[((size_t)c * B + b) * D + t], v);  // 512B coalesced
    }
    g_pvec2[(b * NCG + cg) * D + t] = v;
}

// ---------------------------------------------------------------------------
// K3: stage-2. Grid = B, 128 threads (t = d). Recompute M, SE; epilogue.
// ---------------------------------------------------------------------------
__global__ __launch_bounds__(128) void k_fin2(const float* __restrict__ x,
                                              const float* __restrict__ al,
                                              float* __restrict__ out) {
    __shared__ float red[4];
    __shared__ float sSE;
    const int t = threadIdx.x, lane = t & 31, w = t >> 5;
    const int b = blockIdx.x;

    float c0, c1;
    const float M = block_max_cmax(b, t, lane, w, red, c0, c1);

    float ps = fmaf(__expf(c0 - M), g_csum[b * NCH + t],
                    __expf(c1 - M) * g_csum[b * NCH + t + 128]);
    #pragma unroll
    for (int o = 16; o > 0; o >>= 1) ps += __shfl_xor_sync(0xffffffffu, ps, o);
    if (lane == 0) red[w] = ps;
    __syncthreads();
    if (t == 0) sSE = red[0] + red[1] + red[2] + red[3];
    __syncthreads();

    float v = 0.f;
    #pragma unroll
    for (int cg = 0; cg < NCG; cg++)
        v += g_pvec2[(b * NCG + cg) * D + t];   // MLP=8, coalesced

    float a = al[b];
    float var = 1.f - a;
    out[b * D + t] = (x[b * D + t] - sqrtf(a) * (v / sSE)) * rsqrtf(var);
}

extern "C" void kernel_launch(void* const* d_in, const int* in_sizes, int n_in,
                              void* d_out, int out_size) {
    const float* x  = (const float*)d_in[0];   // inputs [B, D]
    const float* al = (const float*)d_in[1];   // alphas [B]
    const float* y  = (const float*)d_in[2];   // data_batch [N, D]
    float* out = (float*)d_out;                // [B, D]

    const size_t SMEM = (CH * YSTRIDE + B * D + B * CH) * sizeof(float);  // ~98 KB
    cudaFuncSetAttribute(k_chunk, cudaFuncAttributeMaxDynamicSharedMemorySize, (int)SMEM);

    k_chunk<<<NCH, 128, SMEM>>>(x, al, y);
    k_part<<<B * NCG, 128>>>();
    k_fin2<<<B, 128>>>(x, al, out);
}